// round 13
// baseline (speedup 1.0000x reference)
#include <cuda_runtime.h>
#include <cuda_fp16.h>
#include <cstdint>

// ---------------- problem constants ----------------
#define D_IN    1024
#define M_HID   4096
#define BATCH   16384
#define R_LORA  16
#define LSCALE  2.0f

// ---------------- GEMM tiling ----------------
#define BM      256                 // batch rows per CTA
#define BN      128                 // hidden cols per CTA
#define NT      (M_HID / BN)        // 32
#define MT      (BATCH / BM)        // 64
#define NTHREADS 256                // 8 warps: 4 along M x 2 along N
#define NITER   16                  // 8 iters G2' (fp16 acc) + 8 iters G1 (fp32 acc), 128 fp16 K each

// smem: stage = x tile (256 rows x 256B payload) + w tile (128 x 256B), row stride 272B
#define ROWB    272
#define XT      (BM * ROWB)          // 69632
#define WT      (BN * ROWB)          // 34816
#define STAGEB  (XT + WT)            // 104448
#define NSTAGE  2
#define BIAS_OFF (NSTAGE * STAGEB)   // 208896
#define W2_OFF   (BIAS_OFF + BN * 4)
#define RED_OFF  (W2_OFF + BN * 4)
#define SMEM_TOTAL (RED_OFF + BM * 2 * 4 + 16)   // 211984 (incl. election slot)
#define ELECT_OFF  (RED_OFF + BM * 2 * 4)

// correction shift: alpha = 64;  h = (63/64) * (G1 + G2'),  b2' = (64/63)*(we + wh/64)
#define ALPHA     64.0f
#define INV_ALPHA 0.015625f
#define B2_BOOST  (64.0f / 63.0f)
#define G1_SCALE  0.984375f          // 63/64

// prep kernel split: first XBLK blocks convert x, remaining M_HID blocks do W_eff
#define XBLK    ((BATCH * D_IN) / (256 * 8))   // 8192

// ---------------- scratch (static device globals) ----------------
__device__ __align__(1024) __half g_a1[BATCH * D_IN];   // 32 MB : fp16(x)
__device__ __align__(1024) __half g_a2[BATCH * D_IN];   // 32 MB : fp16(xh + 64*xe)
__device__ __align__(1024) __half g_b1[M_HID * D_IN];   //  8 MB : fp16(w_eff)
__device__ __align__(1024) __half g_b2[M_HID * D_IN];   //  8 MB : fp16((64/63)*(we + wh/64))
__device__ float g_partial[NT * BATCH];                 //  2 MB
__device__ int   g_done[MT];                            // zero-init; self-resetting

// ---------------- PTX helpers ----------------
__device__ __forceinline__ uint32_t smem_u32(const void* p) {
    uint32_t a;
    asm("{ .reg .u64 t; cvta.to.shared.u64 t, %1; cvt.u32.u64 %0, t; }"
        : "=r"(a) : "l"(p));
    return a;
}

#define CP_ASYNC16(s, g) \
    asm volatile("cp.async.cg.shared.global [%0], [%1], 16;" :: "r"(s), "l"(g) : "memory")
#define CP_COMMIT() asm volatile("cp.async.commit_group;" ::: "memory")
#define CP_WAIT(n)  asm volatile("cp.async.wait_group %0;" :: "n"(n) : "memory")

__device__ __forceinline__ void ldsm4(uint32_t* r, uint32_t addr) {
    asm volatile("ldmatrix.sync.aligned.m8n8.x4.shared.b16 {%0,%1,%2,%3}, [%4];"
                 : "=r"(r[0]), "=r"(r[1]), "=r"(r[2]), "=r"(r[3]) : "r"(addr));
}

// fp32-accumulator HMMA
__device__ __forceinline__ void mma_f16(float* c, const uint32_t* a, const uint32_t* b) {
    asm volatile(
        "mma.sync.aligned.m16n8k16.row.col.f32.f16.f16.f32 "
        "{%0,%1,%2,%3}, {%4,%5,%6,%7}, {%8,%9}, {%0,%1,%2,%3};"
        : "+f"(c[0]), "+f"(c[1]), "+f"(c[2]), "+f"(c[3])
        : "r"(a[0]), "r"(a[1]), "r"(a[2]), "r"(a[3]), "r"(b[0]), "r"(b[1]));
}

// fp16-accumulator HMMA
__device__ __forceinline__ void mma_f16h(uint32_t* c, const uint32_t* a, const uint32_t* b) {
    asm volatile(
        "mma.sync.aligned.m16n8k16.row.col.f16.f16.f16.f16 "
        "{%0,%1}, {%2,%3,%4,%5}, {%6,%7}, {%0,%1};"
        : "+r"(c[0]), "+r"(c[1])
        : "r"(a[0]), "r"(a[1]), "r"(a[2]), "r"(a[3]), "r"(b[0]), "r"(b[1]));
}

// ==================================================================
// Kernel A (fused prep):
//   blocks [0, XBLK):          x -> a1 = fp16(x), a2 = fp16(xh + 64*xe)
//   blocks [XBLK, XBLK+M_HID): W_eff row -> b1, b2
// ==================================================================
__global__ __launch_bounds__(256) void prep_kernel(
    const float* __restrict__ x, const float* __restrict__ W0,
    const float* __restrict__ A, const float* __restrict__ Bm)
{
    if (blockIdx.x < XBLK) {
        size_t i = (size_t)blockIdx.x * 256 + threadIdx.x;
        size_t base = i * 8;
        float4 v0 = ((const float4*)x)[i * 2];
        float4 v1 = ((const float4*)x)[i * 2 + 1];
        float f[8] = {v0.x, v0.y, v0.z, v0.w, v1.x, v1.y, v1.z, v1.w};
        __half a1[8], a2[8];
#pragma unroll
        for (int j = 0; j < 8; ++j) {
            __half h = __float2half_rn(f[j]);
            float hf = __half2float(h);
            a1[j] = h;
            a2[j] = __float2half_rn(hf + ALPHA * (f[j] - hf));
        }
        *(uint4*)(g_a1 + base) = *(uint4*)a1;
        *(uint4*)(g_a2 + base) = *(uint4*)a2;
    } else {
        int m = blockIdx.x - XBLK;
        float br[R_LORA];
#pragma unroll
        for (int r = 0; r < R_LORA; ++r) br[r] = Bm[m * R_LORA + r] * LSCALE;

        int d4 = threadIdx.x;
        float4 acc = ((const float4*)(W0 + (size_t)m * D_IN))[d4];
#pragma unroll
        for (int r = 0; r < R_LORA; ++r) {
            float4 a = ((const float4*)(A + (size_t)r * D_IN))[d4];
            acc.x = fmaf(br[r], a.x, acc.x);
            acc.y = fmaf(br[r], a.y, acc.y);
            acc.z = fmaf(br[r], a.z, acc.z);
            acc.w = fmaf(br[r], a.w, acc.w);
        }
        float f[4] = {acc.x, acc.y, acc.z, acc.w};
        __half b1[4], b2[4];
#pragma unroll
        for (int j = 0; j < 4; ++j) {
            __half h = __float2half_rn(f[j]);
            float hf = __half2float(h);
            b1[j] = h;
            b2[j] = __float2half_rn(B2_BOOST * ((f[j] - hf) + hf * INV_ALPHA));
        }
        size_t base = (size_t)m * D_IN + d4 * 4;
        *(uint2*)(g_b1 + base) = *(uint2*)b1;
        *(uint2*)(g_b2 + base) = *(uint2*)b2;
    }
}

// ==================================================================
// Kernel C: two-phase fp16 GEMM + fused deterministic final reduction
//   phase A (it 0..7):   G2' = a2 . b2  with fp16 accumulators (hacc)
//   fold:                facc = float(hacc)
//   phase B (it 8..15):  facc += a1 . b1 with fp32 accumulators
//   epilogue:            h = (63/64) * facc; relu-dot with W2 -> g_partial
//   tail:                last CTA per mt sums all 32 nt-partials -> out
// grid (NT=32, MT=64), 256 threads (8 warps: 4 along M x 2 along N)
// ==================================================================
__device__ __forceinline__ void issue_stage(int it, int b0, int n0, int tid, uint32_t sb)
{
    const uint32_t sst = sb + (uint32_t)((it & 1) * STAGEB);
    const __half* xs = (it < 8) ? g_a2 : g_a1;
    const __half* ws = (it < 8) ? g_b2 : g_b1;
    const int ko = (it & 7) * 128;            // 128 halves = 256 bytes per iter
#pragma unroll
    for (int i = 0; i < 16; ++i) {            // X: 4096 16B chunks
        int idx = tid + i * 256;
        int r = idx >> 4, c = idx & 15;
        CP_ASYNC16(sst + (uint32_t)(r * ROWB + c * 16),
                   xs + (size_t)(b0 + r) * D_IN + ko + c * 8);
    }
#pragma unroll
    for (int i = 0; i < 8; ++i) {             // W: 2048 16B chunks
        int idx = tid + i * 256;
        int r = idx >> 4, c = idx & 15;
        CP_ASYNC16(sst + XT + (uint32_t)(r * ROWB + c * 16),
                   ws + (size_t)(n0 + r) * D_IN + ko + c * 8);
    }
}

__global__ void __launch_bounds__(NTHREADS, 1) main_mma_kernel(
    const float* __restrict__ b0v, const float* __restrict__ W2,
    const float* __restrict__ b2v, float* __restrict__ out)
{
    extern __shared__ __align__(128) char smem[];
    const uint32_t sb = smem_u32(smem);
    const int tid  = threadIdx.x;
    const int wid  = tid >> 5;
    const int lane = tid & 31;
    const int wm   = wid >> 1;           // 0..3  (64-row slice)
    const int wn   = wid & 1;            // 0..1  (64-col slice)
    const int n0   = blockIdx.x * BN;
    const int b0   = blockIdx.y * BM;

    if (tid < BN) {
        ((float*)(smem + BIAS_OFF))[tid] = b0v[n0 + tid];
        ((float*)(smem + W2_OFF))[tid]   = W2[n0 + tid];
    }

    const uint32_t aoff = (uint32_t)((lane & 15) * ROWB + (lane >> 4) * 16);
    const uint32_t boff = (uint32_t)((((lane & 7) + ((lane >> 4) << 3)) * ROWB)
                                     + ((lane >> 3) & 1) * 16);

    float facc[4][8][4];

    issue_stage(0, b0, n0, tid, sb); CP_COMMIT();
    issue_stage(1, b0, n0, tid, sb); CP_COMMIT();

    // ---------------- phase A: G2' with fp16 accumulators ----------------
    {
        uint32_t hacc[4][8][2];
#pragma unroll
        for (int mt = 0; mt < 4; ++mt)
#pragma unroll
            for (int nt = 0; nt < 8; ++nt) { hacc[mt][nt][0] = 0u; hacc[mt][nt][1] = 0u; }

        for (int it = 0; it < 8; ++it) {
            CP_WAIT(1);
            __syncthreads();                 // stage it visible to all warps

            const uint32_t st = sb + (uint32_t)((it & 1) * STAGEB);
#pragma unroll
            for (int ks = 0; ks < 8; ++ks) {
                const uint32_t kb = (uint32_t)(ks * 32);
                uint32_t a[4][4], b[4][4];
#pragma unroll
                for (int mt = 0; mt < 4; ++mt)
                    ldsm4(a[mt], st + (uint32_t)((wm * 64 + mt * 16) * ROWB) + kb + aoff);
#pragma unroll
                for (int bt = 0; bt < 4; ++bt)
                    ldsm4(b[bt], st + XT + (uint32_t)((wn * 64 + bt * 16) * ROWB) + kb + boff);
#pragma unroll
                for (int mt = 0; mt < 4; ++mt)
#pragma unroll
                    for (int nt = 0; nt < 8; ++nt)
                        mma_f16h(hacc[mt][nt], a[mt], &b[nt >> 1][(nt & 1) * 2]);
            }

            __syncthreads();                 // everyone done reading stage (it&1)
            if (it + 2 < NITER) {
                issue_stage(it + 2, b0, n0, tid, sb);
                CP_COMMIT();
            }
        }

        // fold: facc = float(hacc)
#pragma unroll
        for (int mt = 0; mt < 4; ++mt)
#pragma unroll
            for (int nt = 0; nt < 8; ++nt) {
                __half2 lo = *(__half2*)&hacc[mt][nt][0];
                __half2 hi = *(__half2*)&hacc[mt][nt][1];
                facc[mt][nt][0] = __low2float(lo);
                facc[mt][nt][1] = __high2float(lo);
                facc[mt][nt][2] = __low2float(hi);
                facc[mt][nt][3] = __high2float(hi);
            }
    }

    // ---------------- phase B: G1 with fp32 accumulators ----------------
    for (int it = 8; it < NITER; ++it) {
        if (it + 1 < NITER) { CP_WAIT(1); } else { CP_WAIT(0); }
        __syncthreads();

        const uint32_t st = sb + (uint32_t)((it & 1) * STAGEB);
#pragma unroll
        for (int ks = 0; ks < 8; ++ks) {
            const uint32_t kb = (uint32_t)(ks * 32);
            uint32_t a[4][4], b[4][4];
#pragma unroll
            for (int mt = 0; mt < 4; ++mt)
                ldsm4(a[mt], st + (uint32_t)((wm * 64 + mt * 16) * ROWB) + kb + aoff);
#pragma unroll
            for (int bt = 0; bt < 4; ++bt)
                ldsm4(b[bt], st + XT + (uint32_t)((wn * 64 + bt * 16) * ROWB) + kb + boff);
#pragma unroll
            for (int mt = 0; mt < 4; ++mt)
#pragma unroll
                for (int nt = 0; nt < 8; ++nt)
                    mma_f16(facc[mt][nt], a[mt], &b[nt >> 1][(nt & 1) * 2]);
        }

        __syncthreads();
        if (it + 2 < NITER) {
            issue_stage(it + 2, b0, n0, tid, sb);
            CP_COMMIT();
        }
    }

    // ---- epilogue: relu((63/64)*facc + bias) . W2, reduce over the 128 local cols ----
    const float* bias = (const float*)(smem + BIAS_OFF);
    const float* w2s  = (const float*)(smem + W2_OFF);
    float* red        = (float*)(smem + RED_OFF);   // [BM][2]
    int*   elect      = (int*)(smem + ELECT_OFF);

#pragma unroll
    for (int mt = 0; mt < 4; ++mt) {
#pragma unroll
        for (int hh = 0; hh < 2; ++hh) {
            float s = 0.f;
#pragma unroll
            for (int nt = 0; nt < 8; ++nt) {
#pragma unroll
                for (int e = 0; e < 2; ++e) {
                    int col = wn * 64 + nt * 8 + (lane & 3) * 2 + e;
                    float hv = facc[mt][nt][hh * 2 + e] * G1_SCALE + bias[col];
                    s = fmaf(fmaxf(hv, 0.f), w2s[col], s);
                }
            }
            s += __shfl_xor_sync(0xffffffffu, s, 1);
            s += __shfl_xor_sync(0xffffffffu, s, 2);
            if ((lane & 3) == 0) {
                int row = wm * 64 + mt * 16 + (lane >> 2) + hh * 8;
                red[row * 2 + wn] = s;
            }
        }
    }
    __syncthreads();

    {
        int row = tid;   // 0..255 = BM rows
        float s = red[row * 2] + red[row * 2 + 1];
        g_partial[(size_t)blockIdx.x * BATCH + b0 + row] = s;
    }

    // ---- fused finalize: last CTA of this mt-group sums all 32 nt-partials ----
    __threadfence();
    if (tid == 0)
        elect[0] = atomicAdd(&g_done[blockIdx.y], 1);
    __syncthreads();
    if (elect[0] == NT - 1) {
        __threadfence();                 // see all other CTAs' g_partial writes
        float s = b2v[0];
        int b = b0 + tid;
#pragma unroll
        for (int t = 0; t < NT; ++t)     // FIXED order -> bitwise deterministic
            s += g_partial[(size_t)t * BATCH + b];
        out[b] = s;
        if (tid == 0) g_done[blockIdx.y] = 0;   // self-reset for next launch
    }
}

// ==================================================================
extern "C" void kernel_launch(void* const* d_in, const int* in_sizes, int n_in,
                              void* d_out, int out_size)
{
    const float* x   = (const float*)d_in[0];
    const float* W0  = (const float*)d_in[1];
    const float* b0v = (const float*)d_in[2];
    const float* A   = (const float*)d_in[3];
    const float* Bm  = (const float*)d_in[4];
    const float* W2  = (const float*)d_in[5];
    const float* b2  = (const float*)d_in[6];
    float* out = (float*)d_out;

    cudaFuncSetAttribute(main_mma_kernel,
                         cudaFuncAttributeMaxDynamicSharedMemorySize, SMEM_TOTAL);

    prep_kernel<<<XBLK + M_HID, 256>>>(x, W0, A, Bm);

    dim3 grid(NT, MT);
    main_mma_kernel<<<grid, NTHREADS, SMEM_TOTAL>>>(b0v, W2, b2, out);
}

// round 14
// speedup vs baseline: 1.0123x; 1.0123x over previous
#include <cuda_runtime.h>
#include <cuda_fp16.h>
#include <cstdint>

// ---------------- problem constants ----------------
#define D_IN    1024
#define M_HID   4096
#define BATCH   16384
#define R_LORA  16
#define LSCALE  2.0f

// ---------------- GEMM tiling ----------------
#define BM      256                 // batch rows per CTA
#define BN      128                 // hidden cols per CTA
#define NT      (M_HID / BN)        // 32
#define MT      (BATCH / BM)        // 64
#define NTHREADS 256                // 8 warps: 4 along M x 2 along N
#define NITER   16                  // 8 iters G2' (fp16 acc) + 8 iters G1 (fp32 acc), 128 fp16 K each

// smem: stage = x tile (256 rows x 256B payload) + w tile (128 x 256B), row stride 272B
#define ROWB    272
#define XT      (BM * ROWB)          // 69632
#define WT      (BN * ROWB)          // 34816
#define STAGEB  (XT + WT)            // 104448
#define NSTAGE  2
#define BIAS_OFF (NSTAGE * STAGEB)   // 208896
#define W2_OFF   (BIAS_OFF + BN * 4)
#define RED_OFF  (W2_OFF + BN * 4)
#define SMEM_TOTAL (RED_OFF + BM * 2 * 4)   // 211968

// correction shift: alpha = 64;  h = (63/64) * (G1 + G2'),  b2' = (64/63)*(we + wh/64)
#define ALPHA     64.0f
#define INV_ALPHA 0.015625f
#define B2_BOOST  (64.0f / 63.0f)
#define G1_SCALE  0.984375f          // 63/64

// prep kernel split: first XBLK blocks convert x (16 floats/thread), rest do W_eff
#define XBLK    ((BATCH * D_IN) / (256 * 16))   // 4096

// ---------------- scratch (static device globals) ----------------
__device__ __align__(1024) __half g_a1[BATCH * D_IN];   // 32 MB : fp16(x)
__device__ __align__(1024) __half g_a2[BATCH * D_IN];   // 32 MB : fp16(xh + 64*xe)
__device__ __align__(1024) __half g_b1[M_HID * D_IN];   //  8 MB : fp16(w_eff)
__device__ __align__(1024) __half g_b2[M_HID * D_IN];   //  8 MB : fp16((64/63)*(we + wh/64))
__device__ float g_partial[NT * BATCH];                 //  2 MB

// ---------------- PTX helpers ----------------
__device__ __forceinline__ uint32_t smem_u32(const void* p) {
    uint32_t a;
    asm("{ .reg .u64 t; cvta.to.shared.u64 t, %1; cvt.u32.u64 %0, t; }"
        : "=r"(a) : "l"(p));
    return a;
}

#define CP_ASYNC16(s, g) \
    asm volatile("cp.async.cg.shared.global [%0], [%1], 16;" :: "r"(s), "l"(g) : "memory")
#define CP_COMMIT() asm volatile("cp.async.commit_group;" ::: "memory")
#define CP_WAIT(n)  asm volatile("cp.async.wait_group %0;" :: "n"(n) : "memory")

__device__ __forceinline__ void ldsm4(uint32_t* r, uint32_t addr) {
    asm volatile("ldmatrix.sync.aligned.m8n8.x4.shared.b16 {%0,%1,%2,%3}, [%4];"
                 : "=r"(r[0]), "=r"(r[1]), "=r"(r[2]), "=r"(r[3]) : "r"(addr));
}

// fp32-accumulator HMMA
__device__ __forceinline__ void mma_f16(float* c, const uint32_t* a, const uint32_t* b) {
    asm volatile(
        "mma.sync.aligned.m16n8k16.row.col.f32.f16.f16.f32 "
        "{%0,%1,%2,%3}, {%4,%5,%6,%7}, {%8,%9}, {%0,%1,%2,%3};"
        : "+f"(c[0]), "+f"(c[1]), "+f"(c[2]), "+f"(c[3])
        : "r"(a[0]), "r"(a[1]), "r"(a[2]), "r"(a[3]), "r"(b[0]), "r"(b[1]));
}

// fp16-accumulator HMMA
__device__ __forceinline__ void mma_f16h(uint32_t* c, const uint32_t* a, const uint32_t* b) {
    asm volatile(
        "mma.sync.aligned.m16n8k16.row.col.f16.f16.f16.f16 "
        "{%0,%1}, {%2,%3,%4,%5}, {%6,%7}, {%0,%1};"
        : "+r"(c[0]), "+r"(c[1])
        : "r"(a[0]), "r"(a[1]), "r"(a[2]), "r"(a[3]), "r"(b[0]), "r"(b[1]));
}

// convert one 8-float chunk to a1/a2 packed halves (numerically identical to
// per-element __float2half_rn; packed cvt halves the instruction count)
__device__ __forceinline__ void split8(const float* f, uint4* a1o, uint4* a2o) {
    uint32_t a1[4], a2[4];
#pragma unroll
    for (int p = 0; p < 4; ++p) {
        __half2 h2 = __floats2half2_rn(f[2 * p], f[2 * p + 1]);
        float2 hf  = __half22float2(h2);
        __half2 c2 = __floats2half2_rn(fmaf(ALPHA, f[2 * p]     - hf.x, hf.x),
                                       fmaf(ALPHA, f[2 * p + 1] - hf.y, hf.y));
        a1[p] = *(uint32_t*)&h2;
        a2[p] = *(uint32_t*)&c2;
    }
    *a1o = *(uint4*)a1;
    *a2o = *(uint4*)a2;
}

// ==================================================================
// Kernel A (fused prep):
//   blocks [0, XBLK):          x -> a1 = fp16(x), a2 = fp16(xh + 64*xe)
//                              16 floats per thread (2 independent chunks)
//   blocks [XBLK, XBLK+M_HID): W_eff row -> b1, b2
// ==================================================================
__global__ __launch_bounds__(256) void prep_kernel(
    const float* __restrict__ x, const float* __restrict__ W0,
    const float* __restrict__ A, const float* __restrict__ Bm)
{
    if (blockIdx.x < XBLK) {
        size_t i = (size_t)blockIdx.x * 256 + threadIdx.x;   // 16-float unit index
        // two independent 8-float chunks, separated to double MLP
        float f0[8], f1[8];
        {
            float4 v0 = ((const float4*)x)[i * 4 + 0];
            float4 v1 = ((const float4*)x)[i * 4 + 1];
            float4 v2 = ((const float4*)x)[i * 4 + 2];
            float4 v3 = ((const float4*)x)[i * 4 + 3];
            f0[0]=v0.x; f0[1]=v0.y; f0[2]=v0.z; f0[3]=v0.w;
            f0[4]=v1.x; f0[5]=v1.y; f0[6]=v1.z; f0[7]=v1.w;
            f1[0]=v2.x; f1[1]=v2.y; f1[2]=v2.z; f1[3]=v2.w;
            f1[4]=v3.x; f1[5]=v3.y; f1[6]=v3.z; f1[7]=v3.w;
        }
        uint4 a1a, a2a, a1b, a2b;
        split8(f0, &a1a, &a2a);
        split8(f1, &a1b, &a2b);
        ((uint4*)g_a1)[i * 2 + 0] = a1a;
        ((uint4*)g_a1)[i * 2 + 1] = a1b;
        ((uint4*)g_a2)[i * 2 + 0] = a2a;
        ((uint4*)g_a2)[i * 2 + 1] = a2b;
    } else {
        int m = blockIdx.x - XBLK;
        float br[R_LORA];
#pragma unroll
        for (int r = 0; r < R_LORA; ++r) br[r] = Bm[m * R_LORA + r] * LSCALE;

        int d4 = threadIdx.x;
        float4 acc = ((const float4*)(W0 + (size_t)m * D_IN))[d4];
#pragma unroll
        for (int r = 0; r < R_LORA; ++r) {
            float4 a = ((const float4*)(A + (size_t)r * D_IN))[d4];
            acc.x = fmaf(br[r], a.x, acc.x);
            acc.y = fmaf(br[r], a.y, acc.y);
            acc.z = fmaf(br[r], a.z, acc.z);
            acc.w = fmaf(br[r], a.w, acc.w);
        }
        float f[4] = {acc.x, acc.y, acc.z, acc.w};
        __half b1[4], b2[4];
#pragma unroll
        for (int j = 0; j < 4; ++j) {
            __half h = __float2half_rn(f[j]);
            float hf = __half2float(h);
            b1[j] = h;
            b2[j] = __float2half_rn(B2_BOOST * ((f[j] - hf) + hf * INV_ALPHA));
        }
        size_t base = (size_t)m * D_IN + d4 * 4;
        *(uint2*)(g_b1 + base) = *(uint2*)b1;
        *(uint2*)(g_b2 + base) = *(uint2*)b2;
    }
}

// ==================================================================
// Kernel C: two-phase fp16 GEMM, BK=64 (256B rows), 2-stage pipeline
//   phase A (it 0..7):   G2' = a2 . b2  with fp16 accumulators (hacc)
//   fold:                facc = float(hacc)
//   phase B (it 8..15):  facc += a1 . b1 with fp32 accumulators
//   epilogue:            h = (63/64) * facc
// grid (NT=32, MT=64), 256 threads (8 warps: 4 along M x 2 along N)
// warp tile 64x64, 256 MMAs per warp between barriers
// ==================================================================
__device__ __forceinline__ void issue_stage(int it, int b0, int n0, int tid, uint32_t sb)
{
    const uint32_t sst = sb + (uint32_t)((it & 1) * STAGEB);
    const __half* xs = (it < 8) ? g_a2 : g_a1;
    const __half* ws = (it < 8) ? g_b2 : g_b1;
    const int ko = (it & 7) * 128;            // 128 halves = 256 bytes per iter
#pragma unroll
    for (int i = 0; i < 16; ++i) {            // X: 4096 16B chunks
        int idx = tid + i * 256;
        int r = idx >> 4, c = idx & 15;
        CP_ASYNC16(sst + (uint32_t)(r * ROWB + c * 16),
                   xs + (size_t)(b0 + r) * D_IN + ko + c * 8);
    }
#pragma unroll
    for (int i = 0; i < 8; ++i) {             // W: 2048 16B chunks
        int idx = tid + i * 256;
        int r = idx >> 4, c = idx & 15;
        CP_ASYNC16(sst + XT + (uint32_t)(r * ROWB + c * 16),
                   ws + (size_t)(n0 + r) * D_IN + ko + c * 8);
    }
}

__global__ void __launch_bounds__(NTHREADS, 1) main_mma_kernel(
    const float* __restrict__ b0v, const float* __restrict__ W2)
{
    extern __shared__ __align__(128) char smem[];
    const uint32_t sb = smem_u32(smem);
    const int tid  = threadIdx.x;
    const int wid  = tid >> 5;
    const int lane = tid & 31;
    const int wm   = wid >> 1;           // 0..3  (64-row slice)
    const int wn   = wid & 1;            // 0..1  (64-col slice)
    const int n0   = blockIdx.x * BN;
    const int b0   = blockIdx.y * BM;

    if (tid < BN) {
        ((float*)(smem + BIAS_OFF))[tid] = b0v[n0 + tid];
        ((float*)(smem + W2_OFF))[tid]   = W2[n0 + tid];
    }

    const uint32_t aoff = (uint32_t)((lane & 15) * ROWB + (lane >> 4) * 16);
    const uint32_t boff = (uint32_t)((((lane & 7) + ((lane >> 4) << 3)) * ROWB)
                                     + ((lane >> 3) & 1) * 16);

    float facc[4][8][4];

    issue_stage(0, b0, n0, tid, sb); CP_COMMIT();
    issue_stage(1, b0, n0, tid, sb); CP_COMMIT();

    // ---------------- phase A: G2' with fp16 accumulators ----------------
    {
        uint32_t hacc[4][8][2];
#pragma unroll
        for (int mt = 0; mt < 4; ++mt)
#pragma unroll
            for (int nt = 0; nt < 8; ++nt) { hacc[mt][nt][0] = 0u; hacc[mt][nt][1] = 0u; }

        for (int it = 0; it < 8; ++it) {
            CP_WAIT(1);
            __syncthreads();                 // stage it visible to all warps

            const uint32_t st = sb + (uint32_t)((it & 1) * STAGEB);
#pragma unroll
            for (int ks = 0; ks < 8; ++ks) {
                const uint32_t kb = (uint32_t)(ks * 32);
                uint32_t a[4][4], b[4][4];
#pragma unroll
                for (int mt = 0; mt < 4; ++mt)
                    ldsm4(a[mt], st + (uint32_t)((wm * 64 + mt * 16) * ROWB) + kb + aoff);
#pragma unroll
                for (int bt = 0; bt < 4; ++bt)
                    ldsm4(b[bt], st + XT + (uint32_t)((wn * 64 + bt * 16) * ROWB) + kb + boff);
#pragma unroll
                for (int mt = 0; mt < 4; ++mt)
#pragma unroll
                    for (int nt = 0; nt < 8; ++nt)
                        mma_f16h(hacc[mt][nt], a[mt], &b[nt >> 1][(nt & 1) * 2]);
            }

            __syncthreads();                 // everyone done reading stage (it&1)
            if (it + 2 < NITER) {
                issue_stage(it + 2, b0, n0, tid, sb);
                CP_COMMIT();
            }
        }

        // fold: facc = float(hacc)
#pragma unroll
        for (int mt = 0; mt < 4; ++mt)
#pragma unroll
            for (int nt = 0; nt < 8; ++nt) {
                __half2 lo = *(__half2*)&hacc[mt][nt][0];
                __half2 hi = *(__half2*)&hacc[mt][nt][1];
                facc[mt][nt][0] = __low2float(lo);
                facc[mt][nt][1] = __high2float(lo);
                facc[mt][nt][2] = __low2float(hi);
                facc[mt][nt][3] = __high2float(hi);
            }
    }

    // ---------------- phase B: G1 with fp32 accumulators ----------------
    for (int it = 8; it < NITER; ++it) {
        if (it + 1 < NITER) { CP_WAIT(1); } else { CP_WAIT(0); }
        __syncthreads();

        const uint32_t st = sb + (uint32_t)((it & 1) * STAGEB);
#pragma unroll
        for (int ks = 0; ks < 8; ++ks) {
            const uint32_t kb = (uint32_t)(ks * 32);
            uint32_t a[4][4], b[4][4];
#pragma unroll
            for (int mt = 0; mt < 4; ++mt)
                ldsm4(a[mt], st + (uint32_t)((wm * 64 + mt * 16) * ROWB) + kb + aoff);
#pragma unroll
            for (int bt = 0; bt < 4; ++bt)
                ldsm4(b[bt], st + XT + (uint32_t)((wn * 64 + bt * 16) * ROWB) + kb + boff);
#pragma unroll
            for (int mt = 0; mt < 4; ++mt)
#pragma unroll
                for (int nt = 0; nt < 8; ++nt)
                    mma_f16(facc[mt][nt], a[mt], &b[nt >> 1][(nt & 1) * 2]);
        }

        __syncthreads();
        if (it + 2 < NITER) {
            issue_stage(it + 2, b0, n0, tid, sb);
            CP_COMMIT();
        }
    }

    // ---- epilogue: relu((63/64)*facc + bias) . W2, reduce over the 128 local cols ----
    const float* bias = (const float*)(smem + BIAS_OFF);
    const float* w2s  = (const float*)(smem + W2_OFF);
    float* red        = (float*)(smem + RED_OFF);   // [BM][2]

#pragma unroll
    for (int mt = 0; mt < 4; ++mt) {
#pragma unroll
        for (int hh = 0; hh < 2; ++hh) {
            float s = 0.f;
#pragma unroll
            for (int nt = 0; nt < 8; ++nt) {
#pragma unroll
                for (int e = 0; e < 2; ++e) {
                    int col = wn * 64 + nt * 8 + (lane & 3) * 2 + e;
                    float hv = facc[mt][nt][hh * 2 + e] * G1_SCALE + bias[col];
                    s = fmaf(fmaxf(hv, 0.f), w2s[col], s);
                }
            }
            s += __shfl_xor_sync(0xffffffffu, s, 1);
            s += __shfl_xor_sync(0xffffffffu, s, 2);
            if ((lane & 3) == 0) {
                int row = wm * 64 + mt * 16 + (lane >> 2) + hh * 8;
                red[row * 2 + wn] = s;
            }
        }
    }
    __syncthreads();

    {
        int row = tid;   // 0..255 = BM rows
        float s = red[row * 2] + red[row * 2 + 1];
        g_partial[(size_t)blockIdx.x * BATCH + b0 + row] = s;
    }
}

// ==================================================================
// Kernel D: out[b] = b2 + sum_nt partial[nt][b]
// ==================================================================
__global__ __launch_bounds__(256) void finalize_kernel(
    const float* __restrict__ b2, float* __restrict__ out)
{
    int b = blockIdx.x * 256 + threadIdx.x;
    float s = b2[0];
#pragma unroll
    for (int t = 0; t < NT; ++t)
        s += g_partial[(size_t)t * BATCH + b];
    out[b] = s;
}

// ==================================================================
extern "C" void kernel_launch(void* const* d_in, const int* in_sizes, int n_in,
                              void* d_out, int out_size)
{
    const float* x   = (const float*)d_in[0];
    const float* W0  = (const float*)d_in[1];
    const float* b0v = (const float*)d_in[2];
    const float* A   = (const float*)d_in[3];
    const float* Bm  = (const float*)d_in[4];
    const float* W2  = (const float*)d_in[5];
    const float* b2  = (const float*)d_in[6];
    float* out = (float*)d_out;

    cudaFuncSetAttribute(main_mma_kernel,
                         cudaFuncAttributeMaxDynamicSharedMemorySize, SMEM_TOTAL);

    prep_kernel<<<XBLK + M_HID, 256>>>(x, W0, A, Bm);

    dim3 grid(NT, MT);
    main_mma_kernel<<<grid, NTHREADS, SMEM_TOTAL>>>(b0v, W2);

    finalize_kernel<<<BATCH / 256, 256>>>(b2, out);
}